// round 7
// baseline (speedup 1.0000x reference)
#include <cuda_runtime.h>
#include <cstdint>

#define BB 128
#define SS 1024
#define EE 512
#define HH 512
#define GG 2048
#define BSH (128*1024*512)

// ---------------- device scratch ----------------
__device__ float    g_xg[(size_t)SS * BB * GG];   // 1 GiB Xg[t][b][g]
__device__ float    g_h[2 * BB * HH];             // double buffered
__device__ float    g_c[BB * HH];
__device__ float    g_biasc[2 * GG];
__device__ int      g_perm[SS * BB];
__device__ int      g_cnt0[SS];
__device__ int      g_base0[SS];
__device__ int      g_base1[SS];
__device__ int      g_flat[1025 * 128];
__device__ int      g_total0_pad;
__device__ unsigned g_count;
__device__ unsigned g_release;

// ---------------- helpers ----------------
__device__ __forceinline__ float tf32r(float x) {
    float r; asm("cvt.rna.tf32.f32 %0, %1;" : "=f"(r) : "f"(x)); return r;
}
__device__ __forceinline__ uint32_t fu(float x) { return __float_as_uint(x); }

__device__ __forceinline__ void mma8(float* d, uint32_t a0, uint32_t a1, uint32_t a2,
                                     uint32_t a3, uint32_t b0, uint32_t b1) {
    asm volatile(
        "mma.sync.aligned.m16n8k8.row.col.f32.tf32.tf32.f32 "
        "{%0,%1,%2,%3},{%4,%5,%6,%7},{%8,%9},{%0,%1,%2,%3};\n"
        : "+f"(d[0]), "+f"(d[1]), "+f"(d[2]), "+f"(d[3])
        : "r"(a0), "r"(a1), "r"(a2), "r"(a3), "r"(b0), "r"(b1));
}

__device__ __forceinline__ float sigm(float x) {
    return __fdividef(1.f, 1.f + __expf(-x));
}

__device__ __forceinline__ void cvt4(float4 v, float4& h, float4& l) {
    h.x = tf32r(v.x); l.x = tf32r(v.x - h.x);
    h.y = tf32r(v.y); l.y = tf32r(v.y - h.y);
    h.z = tf32r(v.z); l.z = tf32r(v.z - h.z);
    h.w = tf32r(v.w); l.w = tf32r(v.w - h.w);
}

// ---------------- setup ----------------
__global__ void k_init(const float* __restrict__ bih, const float* __restrict__ bhh) {
    int i = blockIdx.x * 256 + threadIdx.x;
    if (i < 2 * GG) g_biasc[i] = bih[i] + bhh[i];
    if (i < BB * HH) { g_c[i] = 0.f; g_h[i] = 0.f; g_h[BB * HH + i] = 0.f; }
}

__global__ void k_perm(const int* __restrict__ inp) {
    __shared__ int cs[128];
    int t = blockIdx.x, b = threadIdx.x;
    cs[b] = inp[b * SS + t] & 1;
    __syncthreads();
    if (b == 0) {
        int c = 0;
        for (int x = 0; x < 128; x++) if (!cs[x]) g_perm[t * 128 + c++] = x;
        g_cnt0[t] = c;
        for (int x = 0; x < 128; x++) if (cs[x]) g_perm[t * 128 + c++] = x;
    }
}

__global__ void k_scan() {
    __shared__ int s[1024];
    int i = threadIdx.x;
    int c = g_cnt0[i];
    s[i] = c;
    __syncthreads();
    for (int off = 1; off < 1024; off <<= 1) {
        int v = (i >= off) ? s[i - off] : 0;
        __syncthreads();
        s[i] += v;
        __syncthreads();
    }
    int excl = s[i] - c;
    int tot0 = s[1023];
    int t0p = (tot0 + 127) & ~127;
    g_base0[i] = excl;
    g_base1[i] = t0p + 128 * i - excl;
    if (i == 0) { g_total0_pad = t0p; g_count = 0u; g_release = 0u; }
    int mid = t0p - tot0;
    if (i < mid) g_flat[tot0 + i] = -1;
    int fe = t0p + (SS * BB - tot0);
    int tail = 1025 * 128 - fe;
    if (i < tail) g_flat[fe + i] = -1;
}

__global__ void k_flat() {
    int t = blockIdx.x, i = threadIdx.x;
    int c0 = g_cnt0[t];
    int b = g_perm[t * 128 + i];
    int v = (b << 10) | t;
    if (i < c0) g_flat[g_base0[t] + i] = v;
    else        g_flat[g_base1[t] + (i - c0)] = v;
}

// ---------------- phase 1: Xg = W_ih[cell] x + bias  (tf32x3 gather-GEMM) ----------------
// grid (32, 1025), 256 thr. Tile 128 tokens x 64 gate cols, K=512 in 16 stages of 32.
// smem floats: sAh 2*128*36, sAl same, sBh 2*64*36, sBl same, toks 128
#define SMEM1 ((2*(2*128*36) + 2*(2*64*36) + 128) * 4)

__global__ __launch_bounds__(256) void k_phase1(const float* __restrict__ embed,
                                                const float* __restrict__ Wih) {
    extern __shared__ float sm[];
    float* sAh = sm;                 // 2 x 128 x 36
    float* sAl = sAh + 9216;
    float* sBh = sAl + 9216;         // 2 x 64 x 36
    float* sBl = sBh + 4608;
    int*   toks = (int*)(sBl + 4608);

    const int tid = threadIdx.x, lane = tid & 31, warp = tid >> 5;
    const int wm = warp & 3, wn = warp >> 2;
    const int m0 = blockIdx.y * 128, n0 = blockIdx.x * 64;

    if (tid < 128) toks[tid] = g_flat[m0 + tid];
    __syncthreads();
    const int cell = (m0 >= g_total0_pad) ? 1 : 0;
    const float* Wb = Wih + (size_t)cell * GG * EE;
    const float* biasb = g_biasc + cell * GG;

    const int ar = tid >> 1, asg = tid & 1;
    const int bn = tid >> 2, bo = (tid & 3) * 8;
    const int atok = toks[ar];

    float4 va[4], vb[2];
    {
        if (atok >= 0) {
            const float4* p = (const float4*)(embed + (size_t)atok * EE + asg * 16);
            va[0] = __ldg(p); va[1] = __ldg(p + 1); va[2] = __ldg(p + 2); va[3] = __ldg(p + 3);
        } else va[0] = va[1] = va[2] = va[3] = make_float4(0, 0, 0, 0);
        const float4* q = (const float4*)(Wb + (size_t)(n0 + bn) * EE + bo);
        vb[0] = __ldg(q); vb[1] = __ldg(q + 1);
    }

    float d[2][4][4];
#pragma unroll
    for (int a = 0; a < 2; a++)
#pragma unroll
        for (int b = 0; b < 4; b++)
#pragma unroll
            for (int c = 0; c < 4; c++) d[a][b][c] = 0.f;

    for (int ks = 0; ks < 16; ks++) {
        int buf = ks & 1;
        {
            float4 h, l;
#pragma unroll
            for (int i = 0; i < 4; i++) {
                cvt4(va[i], h, l);
                *(float4*)(sAh + buf * 4608 + ar * 36 + asg * 16 + i * 4) = h;
                *(float4*)(sAl + buf * 4608 + ar * 36 + asg * 16 + i * 4) = l;
            }
#pragma unroll
            for (int i = 0; i < 2; i++) {
                cvt4(vb[i], h, l);
                *(float4*)(sBh + buf * 2304 + bn * 36 + bo + i * 4) = h;
                *(float4*)(sBl + buf * 2304 + bn * 36 + bo + i * 4) = l;
            }
        }
        __syncthreads();
        if (ks < 15) {
            int k0 = (ks + 1) * 32;
            if (atok >= 0) {
                const float4* p = (const float4*)(embed + (size_t)atok * EE + k0 + asg * 16);
                va[0] = __ldg(p); va[1] = __ldg(p + 1); va[2] = __ldg(p + 2); va[3] = __ldg(p + 3);
            }
            const float4* q = (const float4*)(Wb + (size_t)(n0 + bn) * EE + k0 + bo);
            vb[0] = __ldg(q); vb[1] = __ldg(q + 1);
        }
        const float* Ah = sAh + buf * 4608;
        const float* Al = sAl + buf * 4608;
        const float* Bh = sBh + buf * 2304;
        const float* Bl = sBl + buf * 2304;
#pragma unroll
        for (int kc = 0; kc < 4; kc++) {
            int kk = kc * 8 + (lane & 3);
            uint32_t bh[4][2], bl[4][2];
#pragma unroll
            for (int nt = 0; nt < 4; nt++) {
                int n = wn * 32 + nt * 8 + (lane >> 2);
                bh[nt][0] = fu(Bh[n * 36 + kk]); bh[nt][1] = fu(Bh[n * 36 + kk + 4]);
                bl[nt][0] = fu(Bl[n * 36 + kk]); bl[nt][1] = fu(Bl[n * 36 + kk + 4]);
            }
#pragma unroll
            for (int mt = 0; mt < 2; mt++) {
                int r = wm * 32 + mt * 16 + (lane >> 2);
                uint32_t ah0 = fu(Ah[r * 36 + kk]),       ah1 = fu(Ah[(r + 8) * 36 + kk]);
                uint32_t ah2 = fu(Ah[r * 36 + kk + 4]),   ah3 = fu(Ah[(r + 8) * 36 + kk + 4]);
                uint32_t al0 = fu(Al[r * 36 + kk]),       al1 = fu(Al[(r + 8) * 36 + kk]);
                uint32_t al2 = fu(Al[r * 36 + kk + 4]),   al3 = fu(Al[(r + 8) * 36 + kk + 4]);
#pragma unroll
                for (int nt = 0; nt < 4; nt++) {
                    mma8(d[mt][nt], ah0, ah1, ah2, ah3, bh[nt][0], bh[nt][1]);
                    mma8(d[mt][nt], ah0, ah1, ah2, ah3, bl[nt][0], bl[nt][1]);
                    mma8(d[mt][nt], al0, al1, al2, al3, bh[nt][0], bh[nt][1]);
                }
            }
        }
    }

#pragma unroll
    for (int mt = 0; mt < 2; mt++)
#pragma unroll
        for (int half = 0; half < 2; half++) {
            int r = wm * 32 + mt * 16 + (lane >> 2) + half * 8;
            int tok = toks[r];
            if (tok < 0) continue;
            int tt = tok & 1023, b = tok >> 10;
            size_t base = ((size_t)(tt * 128 + b)) * GG;
#pragma unroll
            for (int nt = 0; nt < 4; nt++) {
                int g0 = n0 + wn * 32 + nt * 8 + (lane & 3) * 2;
                float2 v;
                v.x = d[mt][nt][half * 2 + 0] + biasb[g0];
                v.y = d[mt][nt][half * 2 + 1] + biasb[g0 + 1];
                *(float2*)(g_xg + base + g0) = v;
            }
        }
}

// ---------------- phase 2: persistent recurrence ----------------
// 128 CTAs: cell = bx>>6, j0 = (bx&63)*8. N = 32 gate cols ({i,f,g,o} x 8). K = 512.
// smem floats: sWh 32*516, sWl 32*516, sAh 2*128*36, sAl 2*128*36, permS 128
// = 16512+16512+9216+9216+128 = 51584 floats = 206336 B  (R4 bug: macro was 169472)
#define SMEM2 ((2*(32*516) + 2*(2*128*36) + 128) * 4)

__global__ __launch_bounds__(256, 1) void k_phase2(const float* __restrict__ Whh,
                                                   float* __restrict__ out) {
    extern __shared__ float sm[];
    float* sWh = sm;                    // 32 x 516
    float* sWl = sWh + 16512;
    float* sAh = sWl + 16512;           // 2 x 128 x 36
    float* sAl = sAh + 9216;
    int*   permS = (int*)(sAl + 9216);

    const int tid = threadIdx.x, lane = tid & 31, w = tid >> 5;
    const int cell = blockIdx.x >> 6;
    const int j0 = (blockIdx.x & 63) * 8;

    for (int idx = tid; idx < 32 * 512; idx += 256) {
        int n = idx >> 9, k = idx & 511;
        int grow = ((n >> 3) << 9) + j0 + (n & 7);
        float v = Whh[((size_t)cell * GG + grow) * HH + k];
        float h = tf32r(v);
        sWh[n * 516 + k] = h;
        sWl[n * 516 + k] = tf32r(v - h);
    }
    __syncthreads();

    const int ar = tid >> 1, asg = tid & 1;

    for (int t = 0; t < SS; t++) {
        if (tid == 0) {
            unsigned r;
            do { asm volatile("ld.acquire.gpu.u32 %0, [%1];" : "=r"(r) : "l"(&g_release)); }
            while (r < (unsigned)t);
        }
        __syncthreads();

        int cnt0 = g_cnt0[t];
        int Mc = cell ? (128 - cnt0) : cnt0;
        int base = cell ? cnt0 : 0;
        if (tid < 128) permS[tid] = (tid < Mc) ? g_perm[t * 128 + base + tid] : 0;
        __syncthreads();
        const int Mpad = (Mc + 15) & ~15;
        const int rp = (t & 1) ^ 1;
        const bool act = (w * 16) < Mc;
        const bool ald = ar < Mpad;
        const int ab = permS[ar];
        const float* hbase = g_h + (size_t)rp * (BB * HH) + (size_t)ab * HH;

        float d[4][4];
#pragma unroll
        for (int a = 0; a < 4; a++)
#pragma unroll
            for (int b = 0; b < 4; b++) d[a][b] = 0.f;

        float4 va[4];
        if (ald) {
            const float4* p = (const float4*)(hbase + asg * 16);
            va[0] = __ldcg(p); va[1] = __ldcg(p + 1); va[2] = __ldcg(p + 2); va[3] = __ldcg(p + 3);
        }
        for (int ks = 0; ks < 16; ks++) {
            int buf = ks & 1;
            if (ald) {
                float4 h, l;
#pragma unroll
                for (int i = 0; i < 4; i++) {
                    cvt4(va[i], h, l);
                    *(float4*)(sAh + buf * 4608 + ar * 36 + asg * 16 + i * 4) = h;
                    *(float4*)(sAl + buf * 4608 + ar * 36 + asg * 16 + i * 4) = l;
                }
            }
            __syncthreads();
            if (ks < 15 && ald) {
                const float4* p = (const float4*)(hbase + (ks + 1) * 32 + asg * 16);
                va[0] = __ldcg(p); va[1] = __ldcg(p + 1); va[2] = __ldcg(p + 2); va[3] = __ldcg(p + 3);
            }
            if (act) {
                const float* Ah = sAh + buf * 4608;
                const float* Al = sAl + buf * 4608;
#pragma unroll
                for (int kc = 0; kc < 4; kc++) {
                    int kk = kc * 8 + (lane & 3);
                    int kg = ks * 32 + kk;
                    int r0 = w * 16 + (lane >> 2);
                    uint32_t ah0 = fu(Ah[r0 * 36 + kk]),     ah1 = fu(Ah[(r0 + 8) * 36 + kk]);
                    uint32_t ah2 = fu(Ah[r0 * 36 + kk + 4]), ah3 = fu(Ah[(r0 + 8) * 36 + kk + 4]);
                    uint32_t al0 = fu(Al[r0 * 36 + kk]),     al1 = fu(Al[(r0 + 8) * 36 + kk]);
                    uint32_t al2 = fu(Al[r0 * 36 + kk + 4]), al3 = fu(Al[(r0 + 8) * 36 + kk + 4]);
#pragma unroll
                    for (int nt = 0; nt < 4; nt++) {
                        int n = nt * 8 + (lane >> 2);
                        uint32_t bh0 = fu(sWh[n * 516 + kg]), bh1 = fu(sWh[n * 516 + kg + 4]);
                        uint32_t bl0 = fu(sWl[n * 516 + kg]), bl1 = fu(sWl[n * 516 + kg + 4]);
                        mma8(d[nt], ah0, ah1, ah2, ah3, bh0, bh1);
                        mma8(d[nt], ah0, ah1, ah2, ah3, bl0, bl1);
                        mma8(d[nt], al0, al1, al2, al3, bh0, bh1);
                    }
                }
            }
        }

        if (act) {
            int wp = t & 1;
#pragma unroll
            for (int half = 0; half < 2; half++) {
                int rm = w * 16 + (lane >> 2) + half * 8;
                if (rm < Mc) {
                    int b = permS[rm];
                    int jj = j0 + (lane & 3) * 2;
                    size_t xb = ((size_t)(t * 128 + b)) * GG + jj;
                    float2 xi = *(const float2*)(g_xg + xb);
                    float2 xf = *(const float2*)(g_xg + xb + 512);
                    float2 xg = *(const float2*)(g_xg + xb + 1024);
                    float2 xo = *(const float2*)(g_xg + xb + 1536);
                    float2 cc = __ldcg((const float2*)(g_c + b * HH + jj));
                    float i0 = sigm(xi.x + d[0][half * 2]);
                    float i1 = sigm(xi.y + d[0][half * 2 + 1]);
                    float f0 = sigm(xf.x + d[1][half * 2]);
                    float f1 = sigm(xf.y + d[1][half * 2 + 1]);
                    float gg0 = tanhf(xg.x + d[2][half * 2]);
                    float gg1 = tanhf(xg.y + d[2][half * 2 + 1]);
                    float o0 = sigm(xo.x + d[3][half * 2]);
                    float o1 = sigm(xo.y + d[3][half * 2 + 1]);
                    float c0 = f0 * cc.x + i0 * gg0;
                    float c1 = f1 * cc.y + i1 * gg1;
                    float h0 = o0 * tanhf(c0);
                    float h1 = o1 * tanhf(c1);
                    *(float2*)(g_c + b * HH + jj) = make_float2(c0, c1);
                    *(float2*)(g_h + (size_t)wp * (BB * HH) + b * HH + jj) = make_float2(h0, h1);
                    *(float2*)(out + (size_t)b * (SS * HH) + t * HH + jj) = make_float2(h0, h1);
                }
            }
        }
        __threadfence();
        __syncthreads();
        if (tid == 0) {
            unsigned v = atomicAdd(&g_count, 1u) + 1u;
            if (v == 128u * (unsigned)(t + 1)) {
                asm volatile("st.release.gpu.u32 [%0], %1;" :: "l"(&g_release), "r"((unsigned)(t + 1)));
            }
        }
    }
}

__global__ void k_tail(float* __restrict__ out) {
    int i = blockIdx.x * 256 + threadIdx.x;
    if (i < BB * HH) {
        out[(size_t)BSH + i] = g_h[BB * HH + i];            // h_last (t=1023, parity 1)
        out[(size_t)BSH + BB * HH + i] = g_c[i];            // c_last
    }
}

extern "C" void kernel_launch(void* const* d_in, const int* in_sizes, int n_in,
                              void* d_out, int out_size) {
    const int*   inp   = (const int*)d_in[0];
    const float* embed = (const float*)d_in[1];
    const float* Wih   = (const float*)d_in[2];
    const float* Whh   = (const float*)d_in[3];
    const float* bih   = (const float*)d_in[4];
    const float* bhh   = (const float*)d_in[5];
    float* out = (float*)d_out;

    cudaFuncSetAttribute(k_phase1, cudaFuncAttributeMaxDynamicSharedMemorySize, SMEM1);
    cudaFuncSetAttribute(k_phase2, cudaFuncAttributeMaxDynamicSharedMemorySize, SMEM2);

    k_init<<<512, 256>>>(bih, bhh);
    k_perm<<<1024, 128>>>(inp);
    k_scan<<<1, 1024>>>();
    k_flat<<<1024, 128>>>();
    k_phase1<<<dim3(32, 1025), 256, SMEM1>>>(embed, Wih);
    k_phase2<<<128, 256, SMEM2>>>(Whh, out);
    if (out_size >= BSH + 2 * BB * HH) k_tail<<<256, 256>>>(out);
}

// round 11
// speedup vs baseline: 1.7259x; 1.7259x over previous
#include <cuda_runtime.h>
#include <cuda_bf16.h>
#include <cstdint>

#define BB 128
#define SS 1024
#define EE 512
#define HH 512
#define GG 2048
#define BSH (128*1024*512)

// ---------------- device scratch ----------------
__device__ float    g_xg[(size_t)SS * BB * GG];   // 1 GiB Xg[t][b][g]
__device__ float    g_h[2 * BB * HH];             // double buffered
__device__ float    g_c[BB * HH];
__device__ float    g_biasc[2 * GG];
__device__ int      g_perm[SS * BB];
__device__ int      g_cnt0[SS];
__device__ int      g_base0[SS];
__device__ int      g_base1[SS];
__device__ int      g_flat[1025 * 128];
__device__ int      g_total0_pad;
__device__ unsigned g_count;
__device__ unsigned g_release;

// ---------------- helpers ----------------
// bf16 Karp split of two floats -> packed hi u32 + packed lo u32
__device__ __forceinline__ void split2(float x, float y, uint32_t& h, uint32_t& l) {
    unsigned short hx = __bfloat16_as_ushort(__float2bfloat16(x));
    unsigned short hy = __bfloat16_as_ushort(__float2bfloat16(y));
    float fx = __bfloat162float(__ushort_as_bfloat16(hx));
    float fy = __bfloat162float(__ushort_as_bfloat16(hy));
    unsigned short lx = __bfloat16_as_ushort(__float2bfloat16(x - fx));
    unsigned short ly = __bfloat16_as_ushort(__float2bfloat16(y - fy));
    h = ((uint32_t)hy << 16) | hx;
    l = ((uint32_t)ly << 16) | lx;
}

__device__ __forceinline__ void mma16(float* d, uint32_t a0, uint32_t a1, uint32_t a2,
                                      uint32_t a3, uint32_t b0, uint32_t b1) {
    asm volatile(
        "mma.sync.aligned.m16n8k16.row.col.f32.bf16.bf16.f32 "
        "{%0,%1,%2,%3},{%4,%5,%6,%7},{%8,%9},{%0,%1,%2,%3};\n"
        : "+f"(d[0]), "+f"(d[1]), "+f"(d[2]), "+f"(d[3])
        : "r"(a0), "r"(a1), "r"(a2), "r"(a3), "r"(b0), "r"(b1));
}

__device__ __forceinline__ float sigm(float x) {
    return __fdividef(1.f, 1.f + __expf(-x));
}

// ---------------- setup ----------------
__global__ void k_init(const float* __restrict__ bih, const float* __restrict__ bhh) {
    int i = blockIdx.x * 256 + threadIdx.x;
    if (i < 2 * GG) g_biasc[i] = bih[i] + bhh[i];
    if (i < BB * HH) { g_c[i] = 0.f; g_h[i] = 0.f; g_h[BB * HH + i] = 0.f; }
}

__global__ void k_perm(const int* __restrict__ inp) {
    __shared__ int cs[128];
    int t = blockIdx.x, b = threadIdx.x;
    cs[b] = inp[b * SS + t] & 1;
    __syncthreads();
    if (b == 0) {
        int c = 0;
        for (int x = 0; x < 128; x++) if (!cs[x]) g_perm[t * 128 + c++] = x;
        g_cnt0[t] = c;
        for (int x = 0; x < 128; x++) if (cs[x]) g_perm[t * 128 + c++] = x;
    }
}

__global__ void k_scan() {
    __shared__ int s[1024];
    int i = threadIdx.x;
    int c = g_cnt0[i];
    s[i] = c;
    __syncthreads();
    for (int off = 1; off < 1024; off <<= 1) {
        int v = (i >= off) ? s[i - off] : 0;
        __syncthreads();
        s[i] += v;
        __syncthreads();
    }
    int excl = s[i] - c;
    int tot0 = s[1023];
    int t0p = (tot0 + 127) & ~127;
    g_base0[i] = excl;
    g_base1[i] = t0p + 128 * i - excl;
    if (i == 0) { g_total0_pad = t0p; g_count = 0u; g_release = 0u; }
    int mid = t0p - tot0;
    if (i < mid) g_flat[tot0 + i] = -1;
    int fe = t0p + (SS * BB - tot0);
    int tail = 1025 * 128 - fe;
    if (i < tail) g_flat[fe + i] = -1;
}

__global__ void k_flat() {
    int t = blockIdx.x, i = threadIdx.x;
    int c0 = g_cnt0[t];
    int b = g_perm[t * 128 + i];
    int v = (b << 10) | t;
    if (i < c0) g_flat[g_base0[t] + i] = v;
    else        g_flat[g_base1[t] + (i - c0)] = v;
}

// ---------------- phase 1: Xg = W_ih[cell] x + bias  (bf16x3 gather-GEMM) ----------------
// grid (32, 1025), 256 thr. Tile 128 tokens x 64 gate cols, K=512 in 16 stages of 32.
// u32 layout: sAh 2*128*20=5120, sAl 5120, sBh 2*64*20=2560, sBl 2560, toks 128
#define SMEM1 ((5120 + 5120 + 2560 + 2560 + 128) * 4)

__global__ __launch_bounds__(256) void k_phase1(const float* __restrict__ embed,
                                                const float* __restrict__ Wih) {
    extern __shared__ uint32_t smu[];
    uint32_t* sAh = smu;
    uint32_t* sAl = sAh + 5120;
    uint32_t* sBh = sAl + 5120;
    uint32_t* sBl = sBh + 2560;
    int*      toks = (int*)(sBl + 2560);

    const int tid = threadIdx.x, lane = tid & 31, warp = tid >> 5;
    const int wm = warp & 3, wn = warp >> 2;
    const int m0 = blockIdx.y * 128, n0 = blockIdx.x * 64;

    if (tid < 128) toks[tid] = g_flat[m0 + tid];
    __syncthreads();
    const int cell = (m0 >= g_total0_pad) ? 1 : 0;
    const float* Wb = Wih + (size_t)cell * GG * EE;
    const float* biasb = g_biasc + cell * GG;

    const int ar = tid >> 1, asg = tid & 1;        // A: 2 thr/row, 16 floats each
    const int bn = tid >> 2, bq = tid & 3;         // B: 4 thr/row, 8 floats each
    const int atok = toks[ar];

    float4 va[4], vb[2];
    if (atok >= 0) {
        const float4* p = (const float4*)(embed + (size_t)atok * EE + asg * 16);
        va[0] = __ldg(p); va[1] = __ldg(p + 1); va[2] = __ldg(p + 2); va[3] = __ldg(p + 3);
    } else va[0] = va[1] = va[2] = va[3] = make_float4(0, 0, 0, 0);
    {
        const float4* q = (const float4*)(Wb + (size_t)(n0 + bn) * EE + bq * 8);
        vb[0] = __ldg(q); vb[1] = __ldg(q + 1);
    }

    float d[2][4][4];
#pragma unroll
    for (int a = 0; a < 2; a++)
#pragma unroll
        for (int b = 0; b < 4; b++)
#pragma unroll
            for (int c = 0; c < 4; c++) d[a][b][c] = 0.f;

    const int cq = lane & 3, rq = lane >> 2;

    for (int ks = 0; ks < 16; ks++) {
        int buf = ks & 1;
        {
            uint32_t h0, l0, h1, l1;
#pragma unroll
            for (int i = 0; i < 4; i++) {
                split2(va[i].x, va[i].y, h0, l0);
                split2(va[i].z, va[i].w, h1, l1);
                int ai = buf * 2560 + ar * 20 + asg * 8 + i * 2;
                sAh[ai] = h0; sAh[ai + 1] = h1;
                sAl[ai] = l0; sAl[ai + 1] = l1;
            }
#pragma unroll
            for (int i = 0; i < 2; i++) {
                split2(vb[i].x, vb[i].y, h0, l0);
                split2(vb[i].z, vb[i].w, h1, l1);
                int bi = buf * 1280 + bn * 20 + bq * 4 + i * 2;
                sBh[bi] = h0; sBh[bi + 1] = h1;
                sBl[bi] = l0; sBl[bi + 1] = l1;
            }
        }
        __syncthreads();
        if (ks < 15) {
            int k0 = (ks + 1) * 32;
            if (atok >= 0) {
                const float4* p = (const float4*)(embed + (size_t)atok * EE + k0 + asg * 16);
                va[0] = __ldg(p); va[1] = __ldg(p + 1); va[2] = __ldg(p + 2); va[3] = __ldg(p + 3);
            }
            const float4* q = (const float4*)(Wb + (size_t)(n0 + bn) * EE + k0 + bq * 8);
            vb[0] = __ldg(q); vb[1] = __ldg(q + 1);
        }
        const uint32_t* Ah = sAh + buf * 2560;
        const uint32_t* Al = sAl + buf * 2560;
        const uint32_t* Bh = sBh + buf * 1280;
        const uint32_t* Bl = sBl + buf * 1280;
#pragma unroll
        for (int kc = 0; kc < 2; kc++) {
            int kb = kc * 8 + cq;
            uint32_t bh[4][2], bl[4][2];
#pragma unroll
            for (int nt = 0; nt < 4; nt++) {
                int n = wn * 32 + nt * 8 + rq;
                bh[nt][0] = Bh[n * 20 + kb]; bh[nt][1] = Bh[n * 20 + kb + 4];
                bl[nt][0] = Bl[n * 20 + kb]; bl[nt][1] = Bl[n * 20 + kb + 4];
            }
#pragma unroll
            for (int mt = 0; mt < 2; mt++) {
                int r = wm * 32 + mt * 16 + rq;
                uint32_t ah0 = Ah[r * 20 + kb],       ah1 = Ah[(r + 8) * 20 + kb];
                uint32_t ah2 = Ah[r * 20 + kb + 4],   ah3 = Ah[(r + 8) * 20 + kb + 4];
                uint32_t al0 = Al[r * 20 + kb],       al1 = Al[(r + 8) * 20 + kb];
                uint32_t al2 = Al[r * 20 + kb + 4],   al3 = Al[(r + 8) * 20 + kb + 4];
#pragma unroll
                for (int nt = 0; nt < 4; nt++) {
                    mma16(d[mt][nt], ah0, ah1, ah2, ah3, bh[nt][0], bh[nt][1]);
                    mma16(d[mt][nt], ah0, ah1, ah2, ah3, bl[nt][0], bl[nt][1]);
                    mma16(d[mt][nt], al0, al1, al2, al3, bh[nt][0], bh[nt][1]);
                }
            }
        }
    }

#pragma unroll
    for (int mt = 0; mt < 2; mt++)
#pragma unroll
        for (int half = 0; half < 2; half++) {
            int r = wm * 32 + mt * 16 + rq + half * 8;
            int tok = toks[r];
            if (tok < 0) continue;
            int tt = tok & 1023, b = tok >> 10;
            size_t base = ((size_t)(tt * 128 + b)) * GG;
#pragma unroll
            for (int nt = 0; nt < 4; nt++) {
                int g0 = n0 + wn * 32 + nt * 8 + cq * 2;
                float2 v;
                v.x = d[mt][nt][half * 2 + 0] + biasb[g0];
                v.y = d[mt][nt][half * 2 + 1] + biasb[g0 + 1];
                *(float2*)(g_xg + base + g0) = v;
            }
        }
}

// ---------------- phase 2: persistent recurrence (bf16x3) ----------------
// 128 CTAs: cell = bx>>6, j0 = (bx&63)*8. N = 32 gate cols ({i,f,g,o} x 8). K = 512.
// u32: sWh 32*260=8320, sWl 8320, sAh 2*128*20=5120, sAl 5120, perm 128 = 27008 u32
#define SMEM2 ((8320 + 8320 + 5120 + 5120 + 128) * 4)

__global__ __launch_bounds__(256, 1) void k_phase2(const float* __restrict__ Whh,
                                                   float* __restrict__ out) {
    extern __shared__ uint32_t smu[];
    uint32_t* sWh = smu;                 // 32 x 260
    uint32_t* sWl = sWh + 8320;
    uint32_t* sAh = sWl + 8320;          // 2 x 128 x 20
    uint32_t* sAl = sAh + 5120;
    int*      permS = (int*)(sAl + 5120);

    const int tid = threadIdx.x, lane = tid & 31, w = tid >> 5;
    const int cell = blockIdx.x >> 6;
    const int j0 = (blockIdx.x & 63) * 8;

    // W_hh slice -> resident smem, bf16 hi/lo split, packed pairs along K
    for (int idx = tid; idx < 32 * 256; idx += 256) {
        int n = idx >> 8, kp = idx & 255;
        int grow = ((n >> 3) << 9) + j0 + (n & 7);
        float2 v = *(const float2*)(Whh + ((size_t)cell * GG + grow) * HH + kp * 2);
        uint32_t h, l; split2(v.x, v.y, h, l);
        sWh[n * 260 + kp] = h;
        sWl[n * 260 + kp] = l;
    }
    __syncthreads();

    const int ar = tid >> 1, asg = tid & 1;
    const int cq = lane & 3, rq = lane >> 2;

    for (int t = 0; t < SS; t++) {
        if (tid == 0) {
            unsigned r;
            do { asm volatile("ld.acquire.gpu.u32 %0, [%1];" : "=r"(r) : "l"(&g_release)); }
            while (r < (unsigned)t);
        }
        __syncthreads();

        int cnt0 = g_cnt0[t];
        int Mc = cell ? (128 - cnt0) : cnt0;
        int base = cell ? cnt0 : 0;
        if (tid < 128) permS[tid] = (tid < Mc) ? g_perm[t * 128 + base + tid] : 0;
        __syncthreads();
        const int Mpad = (Mc + 15) & ~15;
        const int rp = (t & 1) ^ 1;
        const bool act = (w * 16) < Mc;
        const bool ald = ar < Mpad;
        const int ab = permS[ar];
        const float* hbase = g_h + (size_t)rp * (BB * HH) + (size_t)ab * HH;

        float d[4][4];
#pragma unroll
        for (int a = 0; a < 4; a++)
#pragma unroll
            for (int b = 0; b < 4; b++) d[a][b] = 0.f;

        float4 va[4];
        if (ald) {
            const float4* p = (const float4*)(hbase + asg * 16);
            va[0] = __ldcg(p); va[1] = __ldcg(p + 1); va[2] = __ldcg(p + 2); va[3] = __ldcg(p + 3);
        }
        for (int ks = 0; ks < 16; ks++) {
            int buf = ks & 1;
            if (ald) {
                uint32_t h0, l0, h1, l1;
#pragma unroll
                for (int i = 0; i < 4; i++) {
                    split2(va[i].x, va[i].y, h0, l0);
                    split2(va[i].z, va[i].w, h1, l1);
                    int ai = buf * 2560 + ar * 20 + asg * 8 + i * 2;
                    sAh[ai] = h0; sAh[ai + 1] = h1;
                    sAl[ai] = l0; sAl[ai + 1] = l1;
                }
            }
            __syncthreads();
            if (ks < 15 && ald) {
                const float4* p = (const float4*)(hbase + (ks + 1) * 32 + asg * 16);
                va[0] = __ldcg(p); va[1] = __ldcg(p + 1); va[2] = __ldcg(p + 2); va[3] = __ldcg(p + 3);
            }
            if (act) {
                const uint32_t* Ah = sAh + buf * 2560;
                const uint32_t* Al = sAl + buf * 2560;
                const int r0 = w * 16 + rq;
#pragma unroll
                for (int kc = 0; kc < 2; kc++) {
                    int kb = kc * 8 + cq;
                    int kg = ks * 16 + kb;
                    uint32_t ah0 = Ah[r0 * 20 + kb],     ah1 = Ah[(r0 + 8) * 20 + kb];
                    uint32_t ah2 = Ah[r0 * 20 + kb + 4], ah3 = Ah[(r0 + 8) * 20 + kb + 4];
                    uint32_t al0 = Al[r0 * 20 + kb],     al1 = Al[(r0 + 8) * 20 + kb];
                    uint32_t al2 = Al[r0 * 20 + kb + 4], al3 = Al[(r0 + 8) * 20 + kb + 4];
#pragma unroll
                    for (int nt = 0; nt < 4; nt++) {
                        int n = nt * 8 + rq;
                        uint32_t bh0 = sWh[n * 260 + kg], bh1 = sWh[n * 260 + kg + 4];
                        uint32_t bl0 = sWl[n * 260 + kg], bl1 = sWl[n * 260 + kg + 4];
                        mma16(d[nt], ah0, ah1, ah2, ah3, bh0, bh1);
                        mma16(d[nt], ah0, ah1, ah2, ah3, bl0, bl1);
                        mma16(d[nt], al0, al1, al2, al3, bh0, bh1);
                    }
                }
            }
        }

        if (act) {
            int wp = t & 1;
#pragma unroll
            for (int half = 0; half < 2; half++) {
                int rm = w * 16 + rq + half * 8;
                if (rm < Mc) {
                    int b = permS[rm];
                    int jj = j0 + cq * 2;
                    size_t xb = ((size_t)(t * 128 + b)) * GG + jj;
                    float2 xi = *(const float2*)(g_xg + xb);
                    float2 xf = *(const float2*)(g_xg + xb + 512);
                    float2 xg = *(const float2*)(g_xg + xb + 1024);
                    float2 xo = *(const float2*)(g_xg + xb + 1536);
                    float2 cc = __ldcg((const float2*)(g_c + b * HH + jj));
                    float i0 = sigm(xi.x + d[0][half * 2]);
                    float i1 = sigm(xi.y + d[0][half * 2 + 1]);
                    float f0 = sigm(xf.x + d[1][half * 2]);
                    float f1 = sigm(xf.y + d[1][half * 2 + 1]);
                    float gg0 = tanhf(xg.x + d[2][half * 2]);
                    float gg1 = tanhf(xg.y + d[2][half * 2 + 1]);
                    float o0 = sigm(xo.x + d[3][half * 2]);
                    float o1 = sigm(xo.y + d[3][half * 2 + 1]);
                    float c0 = f0 * cc.x + i0 * gg0;
                    float c1 = f1 * cc.y + i1 * gg1;
                    float h0 = o0 * tanhf(c0);
                    float h1 = o1 * tanhf(c1);
                    *(float2*)(g_c + b * HH + jj) = make_float2(c0, c1);
                    *(float2*)(g_h + (size_t)wp * (BB * HH) + b * HH + jj) = make_float2(h0, h1);
                    *(float2*)(out + (size_t)b * (SS * HH) + t * HH + jj) = make_float2(h0, h1);
                }
            }
        }
        __threadfence();
        __syncthreads();
        if (tid == 0) {
            unsigned v = atomicAdd(&g_count, 1u) + 1u;
            if (v == 128u * (unsigned)(t + 1)) {
                asm volatile("st.release.gpu.u32 [%0], %1;" :: "l"(&g_release), "r"((unsigned)(t + 1)));
            }
        }
    }
}

__global__ void k_tail(float* __restrict__ out) {
    int i = blockIdx.x * 256 + threadIdx.x;
    if (i < BB * HH) {
        out[(size_t)BSH + i] = g_h[BB * HH + i];            // h_last (t=1023, parity 1)
        out[(size_t)BSH + BB * HH + i] = g_c[i];            // c_last
    }
}

extern "C" void kernel_launch(void* const* d_in, const int* in_sizes, int n_in,
                              void* d_out, int out_size) {
    const int*   inp   = (const int*)d_in[0];
    const float* embed = (const float*)d_in[1];
    const float* Wih   = (const float*)d_in[2];
    const float* Whh   = (const float*)d_in[3];
    const float* bih   = (const float*)d_in[4];
    const float* bhh   = (const float*)d_in[5];
    float* out = (float*)d_out;

    cudaFuncSetAttribute(k_phase1, cudaFuncAttributeMaxDynamicSharedMemorySize, SMEM1);
    cudaFuncSetAttribute(k_phase2, cudaFuncAttributeMaxDynamicSharedMemorySize, SMEM2);

    k_init<<<512, 256>>>(bih, bhh);
    k_perm<<<1024, 128>>>(inp);
    k_scan<<<1, 1024>>>();
    k_flat<<<1024, 128>>>();
    k_phase1<<<dim3(32, 1025), 256, SMEM1>>>(embed, Wih);
    k_phase2<<<128, 256, SMEM2>>>(Whh, out);
    if (out_size >= BSH + 2 * BB * HH) k_tail<<<256, 256>>>(out);
}